// round 1
// baseline (speedup 1.0000x reference)
#include <cuda_runtime.h>
#include <math.h>

#define N_B 8
#define L_S 1024
#define DM  1024
#define H   16
#define D   64
#define QT  16
#define THREADS 512
#define SCALE 0.125f   // 1/sqrt(64)

// packed fp32x2 FMA (2x fp32 throughput on sm_103a, PTX-only)
__device__ __forceinline__ void ffma2(float2& acc, float2 a, float2 b) {
    asm("fma.rn.f32x2 %0, %1, %2, %0;"
        : "+l"(*reinterpret_cast<unsigned long long*>(&acc))
        : "l"(*reinterpret_cast<const unsigned long long*>(&a)),
          "l"(*reinterpret_cast<const unsigned long long*>(&b)));
}

// SMEM layout (dynamic):
//   sc  : QT * L_S floats (64KB)  -- score rows / reused as PV partial buffer
//   at  : QT * L_S floats (64KB)  -- attn head-mean accumulator
//   qst : D * QT floats (4KB)     -- Q tile, transposed (d-major), pre-scaled
#define SMEM_FLOATS (QT*L_S*2 + D*QT)

extern "C" __global__ void __launch_bounds__(THREADS, 1)
attn_fused_kernel(const float* __restrict__ in,
                  float* __restrict__ out,
                  float* __restrict__ attn_out,
                  int write_attn)
{
    extern __shared__ float sm[];
    float* sc  = sm;                 // [QT][L_S]
    float* at  = sc + QT * L_S;      // [QT][L_S]
    float* qst = at + QT * L_S;      // [D][QT]

    const int qt   = blockIdx.x;
    const int n    = blockIdx.y;
    const int q0   = qt * QT;
    const int tid  = threadIdx.x;
    const int lane = tid & 31;
    const int warp = tid >> 5;       // 16 warps == QT rows

    // zero attn accumulator
    for (int idx = tid; idx < QT * L_S; idx += THREADS) at[idx] = 0.f;

    const float* base = in + (size_t)n * L_S * DM;

    for (int h = 0; h < H; ++h) {
        // ---- load Q tile transposed + pre-scaled ----
        __syncthreads();  // previous head done with qst / sc
        for (int idx = tid; idx < QT * D; idx += THREADS) {
            int i = idx >> 6, d = idx & 63;
            qst[d * QT + i] = base[(size_t)(q0 + i) * DM + h * D + d] * SCALE;
        }
        __syncthreads();

        // ---- QK^T : each thread computes 2 s-columns for all 16 rows ----
        #pragma unroll
        for (int sb = 0; sb < 2; ++sb) {
            const int s = tid + sb * THREADS;
            const float4* krow =
                reinterpret_cast<const float4*>(base + (size_t)s * DM + h * D);
            float2 acc[8];
            #pragma unroll
            for (int p = 0; p < 8; ++p) acc[p] = make_float2(0.f, 0.f);

            #pragma unroll
            for (int d4 = 0; d4 < 16; ++d4) {
                const float4 kv = krow[d4];
                const float kvs[4] = {kv.x, kv.y, kv.z, kv.w};
                #pragma unroll
                for (int dc = 0; dc < 4; ++dc) {
                    const float2 kk = make_float2(kvs[dc], kvs[dc]);
                    const float2* q2 =
                        reinterpret_cast<const float2*>(qst + (d4 * 4 + dc) * QT);
                    #pragma unroll
                    for (int p = 0; p < 8; ++p) ffma2(acc[p], q2[p], kk);
                }
            }
            #pragma unroll
            for (int p = 0; p < 8; ++p) {
                sc[(2 * p)     * L_S + s] = acc[p].x;
                sc[(2 * p + 1) * L_S + s] = acc[p].y;
            }
        }
        __syncthreads();

        // ---- softmax per row (warp w owns row w), fold into attn accum ----
        {
            float* row = sc + warp * L_S;
            float m = -1e30f;
            for (int s = lane; s < L_S; s += 32) m = fmaxf(m, row[s]);
            #pragma unroll
            for (int o = 16; o > 0; o >>= 1)
                m = fmaxf(m, __shfl_xor_sync(0xffffffffu, m, o));
            float sum = 0.f;
            for (int s = lane; s < L_S; s += 32) {
                float e = __expf(row[s] - m);
                row[s] = e;
                sum += e;
            }
            #pragma unroll
            for (int o = 16; o > 0; o >>= 1)
                sum += __shfl_xor_sync(0xffffffffu, sum, o);
            const float inv = 1.f / sum;
            float* arow = at + warp * L_S;
            for (int s = lane; s < L_S; s += 32) {
                float p = row[s] * inv;
                row[s]  = p;
                arow[s] += p;
            }
        }
        __syncthreads();

        // ---- P @ V : warp g owns s-range [g*64, g*64+64); each thread keeps
        //      all 16 rows for one float2 head-dim column (v reused 16x) ----
        {
            const int c   = lane;        // float2 column 0..31
            const int g   = warp;        // s-group 0..15
            const int dd0 = c * 2;
            const float* vbase = base + h * D + dd0;
            float2 acc[16];
            #pragma unroll
            for (int i = 0; i < 16; ++i) acc[i] = make_float2(0.f, 0.f);

            const int s0 = g * 64;
            #pragma unroll 4
            for (int s = 0; s < 64; ++s) {
                const float2 v =
                    *reinterpret_cast<const float2*>(vbase + (size_t)(s0 + s) * DM);
                #pragma unroll
                for (int i = 0; i < 16; ++i) {
                    const float p = sc[i * L_S + s0 + s];
                    ffma2(acc[i], v, make_float2(p, p));
                }
            }
            __syncthreads();   // all warps done reading sc

            // partials into sc (reused): part[g*512 + i*32 + c] (float2 units)
            float2* part = reinterpret_cast<float2*>(sc);
            #pragma unroll
            for (int i = 0; i < 16; ++i) part[g * 512 + i * 32 + c] = acc[i];
            __syncthreads();

            // cross-warp reduce: thread o handles output float2 o
            const int o  = tid;          // 0..511 = i*32 + c2
            const int oi = o >> 5;
            const int oc = o & 31;
            float2 r = part[o];
            #pragma unroll
            for (int gg = 1; gg < 16; ++gg) {
                float2 p2 = part[gg * 512 + o];
                r.x += p2.x; r.y += p2.y;
            }
            *reinterpret_cast<float2*>(
                out + (size_t)(n * L_S + q0 + oi) * DM + h * D + oc * 2) = r;
        }
    }

    __syncthreads();
    // ---- write head-averaged attention weights ----
    if (write_attn) {
        float* aout = attn_out + ((size_t)n * L_S + q0) * L_S;
        for (int idx = tid; idx < QT * L_S; idx += THREADS) {
            int i = idx >> 10, s = idx & 1023;
            aout[(size_t)i * L_S + s] = at[idx] * (1.f / 16.f);
        }
    }
}

extern "C" void kernel_launch(void* const* d_in, const int* in_sizes, int n_in,
                              void* d_out, int out_size) {
    const float* in = (const float*)d_in[0];
    float* out = (float*)d_out;
    const size_t out_elems  = (size_t)N_B * L_S * DM;       // 8,388,608
    const size_t attn_elems = (size_t)N_B * L_S * L_S;      // 8,388,608
    int write_attn = (out_size >= (int)(out_elems + attn_elems)) ? 1 : 0;
    float* attn = out + out_elems;

    const int smem_bytes = SMEM_FLOATS * sizeof(float);     // ~132 KB
    cudaFuncSetAttribute(attn_fused_kernel,
                         cudaFuncAttributeMaxDynamicSharedMemorySize, smem_bytes);

    dim3 grid(L_S / QT, N_B);   // (64, 8)
    attn_fused_kernel<<<grid, THREADS, smem_bytes>>>(in, out, attn, write_attn);
}

// round 2
// speedup vs baseline: 1.0018x; 1.0018x over previous
#include <cuda_runtime.h>
#include <math.h>

#define N_B 8
#define L_S 1024
#define DM  1024
#define H   16
#define D   64
#define QT  16
#define THREADS 512
#define SCALE 0.125f   // 1/sqrt(64)

// packed fp32x2 FMA (2x fp32 throughput on sm_103a, PTX-only)
__device__ __forceinline__ void ffma2(float2& acc, float2 a, float2 b) {
    asm("fma.rn.f32x2 %0, %1, %2, %0;"
        : "+l"(*reinterpret_cast<unsigned long long*>(&acc))
        : "l"(*reinterpret_cast<const unsigned long long*>(&a)),
          "l"(*reinterpret_cast<const unsigned long long*>(&b)));
}

// SMEM layout (dynamic):
//   sc  : QT * L_S floats (64KB)  -- score rows / reused as PV partial buffer
//   at  : QT * L_S floats (64KB)  -- attn head-mean accumulator
//   qst : D * QT floats (4KB)     -- Q tile, transposed (d-major), pre-scaled
#define SMEM_FLOATS (QT*L_S*2 + D*QT)

extern "C" __global__ void __launch_bounds__(THREADS, 1)
attn_fused_kernel(const float* __restrict__ in,
                  float* __restrict__ out,
                  float* __restrict__ attn_out,
                  int write_attn)
{
    extern __shared__ float sm[];
    float* sc  = sm;                 // [QT][L_S]
    float* at  = sc + QT * L_S;      // [QT][L_S]
    float* qst = at + QT * L_S;      // [D][QT]

    const int qt   = blockIdx.x;
    const int n    = blockIdx.y;
    const int q0   = qt * QT;
    const int tid  = threadIdx.x;
    const int lane = tid & 31;
    const int warp = tid >> 5;       // 16 warps == QT rows

    // zero attn accumulator
    for (int idx = tid; idx < QT * L_S; idx += THREADS) at[idx] = 0.f;

    const float* base = in + (size_t)n * L_S * DM;

    for (int h = 0; h < H; ++h) {
        // ---- load Q tile transposed + pre-scaled ----
        __syncthreads();  // previous head done with qst / sc
        for (int idx = tid; idx < QT * D; idx += THREADS) {
            int i = idx >> 6, d = idx & 63;
            qst[d * QT + i] = base[(size_t)(q0 + i) * DM + h * D + d] * SCALE;
        }
        __syncthreads();

        // ---- QK^T : each thread computes 2 s-columns for all 16 rows ----
        #pragma unroll
        for (int sb = 0; sb < 2; ++sb) {
            const int s = tid + sb * THREADS;
            const float4* krow =
                reinterpret_cast<const float4*>(base + (size_t)s * DM + h * D);
            float2 acc[8];
            #pragma unroll
            for (int p = 0; p < 8; ++p) acc[p] = make_float2(0.f, 0.f);

            #pragma unroll
            for (int d4 = 0; d4 < 16; ++d4) {
                const float4 kv = krow[d4];
                const float kvs[4] = {kv.x, kv.y, kv.z, kv.w};
                #pragma unroll
                for (int dc = 0; dc < 4; ++dc) {
                    const float2 kk = make_float2(kvs[dc], kvs[dc]);
                    const float2* q2 =
                        reinterpret_cast<const float2*>(qst + (d4 * 4 + dc) * QT);
                    #pragma unroll
                    for (int p = 0; p < 8; ++p) ffma2(acc[p], q2[p], kk);
                }
            }
            #pragma unroll
            for (int p = 0; p < 8; ++p) {
                sc[(2 * p)     * L_S + s] = acc[p].x;
                sc[(2 * p + 1) * L_S + s] = acc[p].y;
            }
        }
        __syncthreads();

        // ---- softmax per row (warp w owns row w), fold into attn accum ----
        {
            float* row = sc + warp * L_S;
            float m = -1e30f;
            for (int s = lane; s < L_S; s += 32) m = fmaxf(m, row[s]);
            #pragma unroll
            for (int o = 16; o > 0; o >>= 1)
                m = fmaxf(m, __shfl_xor_sync(0xffffffffu, m, o));
            float sum = 0.f;
            for (int s = lane; s < L_S; s += 32) {
                float e = __expf(row[s] - m);
                row[s] = e;
                sum += e;
            }
            #pragma unroll
            for (int o = 16; o > 0; o >>= 1)
                sum += __shfl_xor_sync(0xffffffffu, sum, o);
            const float inv = 1.f / sum;
            float* arow = at + warp * L_S;
            for (int s = lane; s < L_S; s += 32) {
                float p = row[s] * inv;
                row[s]  = p;
                arow[s] += p;
            }
        }
        __syncthreads();

        // ---- P @ V : warp g owns s-range [g*64, g*64+64); each thread keeps
        //      all 16 rows for one float2 head-dim column (v reused 16x) ----
        {
            const int c   = lane;        // float2 column 0..31
            const int g   = warp;        // s-group 0..15
            const int dd0 = c * 2;
            const float* vbase = base + h * D + dd0;
            float2 acc[16];
            #pragma unroll
            for (int i = 0; i < 16; ++i) acc[i] = make_float2(0.f, 0.f);

            const int s0 = g * 64;
            #pragma unroll 4
            for (int s = 0; s < 64; ++s) {
                const float2 v =
                    *reinterpret_cast<const float2*>(vbase + (size_t)(s0 + s) * DM);
                #pragma unroll
                for (int i = 0; i < 16; ++i) {
                    const float p = sc[i * L_S + s0 + s];
                    ffma2(acc[i], v, make_float2(p, p));
                }
            }
            __syncthreads();   // all warps done reading sc

            // partials into sc (reused): part[g*512 + i*32 + c] (float2 units)
            float2* part = reinterpret_cast<float2*>(sc);
            #pragma unroll
            for (int i = 0; i < 16; ++i) part[g * 512 + i * 32 + c] = acc[i];
            __syncthreads();

            // cross-warp reduce: thread o handles output float2 o
            const int o  = tid;          // 0..511 = i*32 + c2
            const int oi = o >> 5;
            const int oc = o & 31;
            float2 r = part[o];
            #pragma unroll
            for (int gg = 1; gg < 16; ++gg) {
                float2 p2 = part[gg * 512 + o];
                r.x += p2.x; r.y += p2.y;
            }
            *reinterpret_cast<float2*>(
                out + (size_t)(n * L_S + q0 + oi) * DM + h * D + oc * 2) = r;
        }
    }

    __syncthreads();
    // ---- write head-averaged attention weights ----
    if (write_attn) {
        float* aout = attn_out + ((size_t)n * L_S + q0) * L_S;
        for (int idx = tid; idx < QT * L_S; idx += THREADS) {
            int i = idx >> 10, s = idx & 1023;
            aout[(size_t)i * L_S + s] = at[idx] * (1.f / 16.f);
        }
    }
}

extern "C" void kernel_launch(void* const* d_in, const int* in_sizes, int n_in,
                              void* d_out, int out_size) {
    const float* in = (const float*)d_in[0];
    float* out = (float*)d_out;
    const size_t out_elems  = (size_t)N_B * L_S * DM;       // 8,388,608
    const size_t attn_elems = (size_t)N_B * L_S * L_S;      // 8,388,608
    int write_attn = (out_size >= (int)(out_elems + attn_elems)) ? 1 : 0;
    float* attn = out + out_elems;

    const int smem_bytes = SMEM_FLOATS * sizeof(float);     // ~132 KB
    cudaFuncSetAttribute(attn_fused_kernel,
                         cudaFuncAttributeMaxDynamicSharedMemorySize, smem_bytes);

    dim3 grid(L_S / QT, N_B);   // (64, 8)
    attn_fused_kernel<<<grid, THREADS, smem_bytes>>>(in, out, attn, write_attn);
}

// round 3
// speedup vs baseline: 3.5234x; 3.5170x over previous
#include <cuda_runtime.h>
#include <math.h>

#define N_B 8
#define L_S 1024
#define DM  1024
#define H   16
#define D   64
#define QT  16
#define THREADS 512
#define SCALE 0.125f     // 1/sqrt(64)
#define CHUNK 512        // s-rows staged per chunk
#define KTS 513          // kT row stride in floats (pad for banks)
#define SCS 18           // scT row stride in floats (pad for banks, 8B-aligned)

// SMEM (floats):
//   kT  : D * KTS      = 32832   (K/V chunk, d-major, transposed)
//   scT : L_S * SCS    = 18432   (scores, s-major rows of 16 q; reused as reduce buf)
//   qs  : D * QT       = 1024    (Q tile, d-major, pre-scaled)
#define SM_KT   0
#define SM_SCT  (D * KTS)
#define SM_QS   (SM_SCT + L_S * SCS)
#define SM_TOT  (SM_QS + D * QT)          // 52288 floats = 209152 B

// packed fp32x2 FMA (2x fp32 throughput on sm_103a, PTX-only)
__device__ __forceinline__ void ffma2(float2& acc, float2 a, float2 b) {
    asm("fma.rn.f32x2 %0, %1, %2, %0;"
        : "+l"(*reinterpret_cast<unsigned long long*>(&acc))
        : "l"(*reinterpret_cast<const unsigned long long*>(&a)),
          "l"(*reinterpret_cast<const unsigned long long*>(&b)));
}

// Stage one 512s x 64d chunk of K (= V) into kT, transposed to d-major.
// gsrc = base + c*CHUNK*DM + h*D. Coalesced LDG.128; STS ~2-way conflict.
__device__ __forceinline__ void stage_k(float* kT, const float* gsrc, int tid) {
    const float4* g4 = reinterpret_cast<const float4*>(gsrc);
    #pragma unroll
    for (int half = 0; half < 2; ++half) {
        float4 buf[8];
        #pragma unroll
        for (int it = 0; it < 8; ++it) {
            int f = (half * 8 + it) * THREADS + tid;   // float4 index in chunk
            int s = f >> 4, d4 = f & 15;               // 16 float4 per row
            buf[it] = g4[(size_t)s * (DM / 4) + d4];
        }
        #pragma unroll
        for (int it = 0; it < 8; ++it) {
            int f = (half * 8 + it) * THREADS + tid;
            int s = f >> 4, d4 = f & 15;
            float* dst = kT + s + (d4 * 4) * KTS;
            dst[0 * KTS] = buf[it].x;
            dst[1 * KTS] = buf[it].y;
            dst[2 * KTS] = buf[it].z;
            dst[3 * KTS] = buf[it].w;
        }
    }
}

extern "C" __global__ void __launch_bounds__(THREADS, 1)
attn_fused_kernel(const float* __restrict__ in,
                  float* __restrict__ out,
                  float* __restrict__ attn_out,
                  int write_attn)
{
    extern __shared__ float sm[];
    float* kT  = sm + SM_KT;
    float* scT = sm + SM_SCT;
    float* qs  = sm + SM_QS;

    const int qt   = blockIdx.x;
    const int n    = blockIdx.y;
    const int q0   = qt * QT;
    const int tid  = threadIdx.x;
    const int lane = tid & 31;
    const int warp = tid >> 5;       // 16 warps == QT rows (softmax: warp owns row)

    const float* base = in + (size_t)n * L_S * DM;

    // head-mean attention accumulator in registers:
    // warp w owns q-row w; at_reg[k] accumulates p[w][lane + 32k]
    float at_reg[32];
    #pragma unroll
    for (int k = 0; k < 32; ++k) at_reg[k] = 0.f;

    for (int h = 0; h < H; ++h) {
        // ---- Q tile, d-major, pre-scaled ----
        __syncthreads();                       // prev head done with qs/scT
        for (int idx = tid; idx < QT * D; idx += THREADS) {
            int i = idx >> 6, d = idx & 63;
            qs[d * QT + i] = base[(size_t)(q0 + i) * DM + h * D + d] * SCALE;
        }

        // ---- QK^T over 2 s-chunks, K staged through SMEM ----
        for (int c = 0; c < 2; ++c) {
            __syncthreads();
            stage_k(kT, base + (size_t)c * CHUNK * DM + h * D, tid);
            __syncthreads();
            // thread owns s_local = tid; computes all 16 q
            float2 acc[8];
            #pragma unroll
            for (int p = 0; p < 8; ++p) acc[p] = make_float2(0.f, 0.f);
            #pragma unroll 8
            for (int d = 0; d < D; ++d) {
                const float kv = kT[d * KTS + tid];          // conflict-free
                const float2 kk = make_float2(kv, kv);
                const float2* q2 = reinterpret_cast<const float2*>(qs + d * QT);
                #pragma unroll
                for (int p = 0; p < 8; ++p) ffma2(acc[p], q2[p], kk);  // broadcast LDS
            }
            float* dstrow = scT + (size_t)(c * CHUNK + tid) * SCS;
            #pragma unroll
            for (int p = 0; p < 8; ++p)
                *reinterpret_cast<float2*>(dstrow + 2 * p) = acc[p];
        }
        __syncthreads();

        // ---- softmax: warp w owns row w; scT[s][w], s strided by lane ----
        {
            float vals[32];
            float m = -1e30f;
            #pragma unroll
            for (int k = 0; k < 32; ++k) {
                vals[k] = scT[(size_t)(lane + 32 * k) * SCS + warp];
                m = fmaxf(m, vals[k]);
            }
            #pragma unroll
            for (int o = 16; o > 0; o >>= 1)
                m = fmaxf(m, __shfl_xor_sync(0xffffffffu, m, o));
            float sum = 0.f;
            #pragma unroll
            for (int k = 0; k < 32; ++k) {
                vals[k] = __expf(vals[k] - m);
                sum += vals[k];
            }
            #pragma unroll
            for (int o = 16; o > 0; o >>= 1)
                sum += __shfl_xor_sync(0xffffffffu, sum, o);
            const float inv = 1.f / sum;
            #pragma unroll
            for (int k = 0; k < 32; ++k) {
                float p = vals[k] * inv;
                scT[(size_t)(lane + 32 * k) * SCS + warp] = p;
                at_reg[k] += p;
            }
        }

        // ---- P @ V (V == K, restaged): lane owns head-dim float2 (2c,2c+1),
        //      warp owns 32 s per chunk; all 16 q rows per thread ----
        float2 pvacc[16];
        #pragma unroll
        for (int i = 0; i < 16; ++i) pvacc[i] = make_float2(0.f, 0.f);

        for (int c = 0; c < 2; ++c) {
            __syncthreads();
            stage_k(kT, base + (size_t)c * CHUNK * DM + h * D, tid);
            __syncthreads();
            const int s0 = warp * 32;
            const float* v0 = kT + (2 * lane) * KTS;
            const float* v1 = kT + (2 * lane + 1) * KTS;
            #pragma unroll 4
            for (int j = 0; j < 32; ++j) {
                const int sl = s0 + j;
                const float2 v = make_float2(v0[sl], v1[sl]);   // 2-way conflict
                const float2* prow =
                    reinterpret_cast<const float2*>(scT + (size_t)(c * CHUNK + sl) * SCS);
                #pragma unroll
                for (int i = 0; i < 8; ++i) {
                    const float2 p2 = prow[i];                  // broadcast LDS.64
                    ffma2(pvacc[2 * i],     v, make_float2(p2.x, p2.x));
                    ffma2(pvacc[2 * i + 1], v, make_float2(p2.y, p2.y));
                }
            }
        }
        __syncthreads();   // everyone done with scT (p values)

        // ---- cross-warp reduce via scT region, then coalesced store ----
        {
            float2* red = reinterpret_cast<float2*>(scT);   // 16*16*32 float2 = 64KB
            #pragma unroll
            for (int i = 0; i < 16; ++i)
                red[(warp * 16 + i) * 32 + lane] = pvacc[i];
            __syncthreads();
            const int oi = tid >> 5, oc = tid & 31;
            float2 r = make_float2(0.f, 0.f);
            #pragma unroll
            for (int g = 0; g < 16; ++g) {
                const float2 p = red[(g * 16 + oi) * 32 + oc];
                r.x += p.x; r.y += p.y;
            }
            *reinterpret_cast<float2*>(
                out + (size_t)(n * L_S + q0 + oi) * DM + h * D + oc * 2) = r;
        }
    }

    // ---- head-averaged attention weights (warp w owns row w) ----
    if (write_attn) {
        float* aout = attn_out + ((size_t)n * L_S + q0 + warp) * L_S;
        #pragma unroll
        for (int k = 0; k < 32; ++k)
            aout[lane + 32 * k] = at_reg[k] * (1.f / 16.f);
    }
}

extern "C" void kernel_launch(void* const* d_in, const int* in_sizes, int n_in,
                              void* d_out, int out_size) {
    const float* in = (const float*)d_in[0];
    float* out = (float*)d_out;
    const size_t out_elems  = (size_t)N_B * L_S * DM;       // 8,388,608
    const size_t attn_elems = (size_t)N_B * L_S * L_S;      // 8,388,608
    int write_attn = (out_size >= (int)(out_elems + attn_elems)) ? 1 : 0;
    float* attn = out + out_elems;

    const int smem_bytes = SM_TOT * sizeof(float);          // 209152 B
    cudaFuncSetAttribute(attn_fused_kernel,
                         cudaFuncAttributeMaxDynamicSharedMemorySize, smem_bytes);

    dim3 grid(L_S / QT, N_B);   // (64, 8)
    attn_fused_kernel<<<grid, THREADS, smem_bytes>>>(in, out, attn, write_attn);
}